// round 3
// baseline (speedup 1.0000x reference)
#include <cuda_runtime.h>

#define SEQ   1024
#define BATCH 512
#define NT    64

// Per-batch log-likelihoods (scratch; device global, no allocation).
__device__ float g_llh[BATCH];

// ---- Blackwell packed f32x2 helpers ----
__device__ __forceinline__ unsigned long long pack2(float lo, float hi) {
    unsigned long long r;
    asm("mov.b64 %0, {%1,%2};" : "=l"(r) : "f"(lo), "f"(hi));
    return r;
}
__device__ __forceinline__ void unpack2(unsigned long long v, float& lo, float& hi) {
    asm("mov.b64 {%0,%1}, %2;" : "=f"(lo), "=f"(hi) : "l"(v));
}
__device__ __forceinline__ unsigned long long fma2(unsigned long long a,
                                                   unsigned long long b,
                                                   unsigned long long c) {
    unsigned long long d;
    asm("fma.rn.f32x2 %0, %1, %2, %3;" : "=l"(d) : "l"(a), "l"(b), "l"(c));
    return d;
}
__device__ __forceinline__ unsigned long long add2(unsigned long long a,
                                                   unsigned long long b) {
    unsigned long long d;
    asm("add.rn.f32x2 %0, %1, %2;" : "=l"(d) : "l"(a), "l"(b));
    return d;
}

__global__ void __launch_bounds__(NT)
crf_forward_kernel(const float* __restrict__ em,
                   const void* __restrict__ tags_raw,
                   const int* __restrict__ mask,
                   const float* __restrict__ startT,
                   const float* __restrict__ endT,
                   const float* __restrict__ trans)
{
    const int b    = blockIdx.x;     // one batch element per block
    const int j    = threadIdx.x;    // tag index 0..63
    const int lane = j & 31;
    const int w    = j >> 5;

    __shared__ float sh_e[2][NT];    // double-buffered beta (linear domain)
    __shared__ float sh_num[2];      // per-warp numerator partials
    __shared__ int   sh_len[2];      // per-warp length partials
    __shared__ float sh_sum[2];      // final sum partials

    // ---- tags dtype detection: int64 => every odd 32-bit word is 0 ----
    const int*       t32 = (const int*)tags_raw;
    const long long* t64 = (const long long*)tags_raw;
    bool is64 = true;
#pragma unroll
    for (int k = 0; k < 16; ++k)
        is64 = is64 && (t32[2 * k * 1031 + 1] == 0);

    // ---- exp(transitions) column j, packed as 32 f32x2 pairs over i ----
    unsigned long long eT2[NT / 2];
#pragma unroll
    for (int i = 0; i < NT / 2; ++i) {
        const float lo = __expf(trans[(2 * i + 0) * NT + j]);
        const float hi = __expf(trans[(2 * i + 1) * NT + j]);
        eT2[i] = pack2(lo, hi);
    }

    // ---- sequence length (mask is monotone: mask[t] = t < length) ----
    int cnt = 0;
    for (int t = j; t < SEQ; t += NT)
        cnt += mask[t * BATCH + b];
#pragma unroll
    for (int o = 16; o > 0; o >>= 1)
        cnt += __shfl_xor_sync(0xffffffffu, cnt, o);
    if (lane == 0) sh_len[w] = cnt;
    __syncthreads();
    const int length = sh_len[0] + sh_len[1];

    // ---- numerator partials: t in [1, length) ----
    float num = 0.f;
    if (is64) {
        for (int t = 1 + j; t < length; t += NT) {
            const int pt = (int)t64[(t - 1) * BATCH + b];
            const int ct = (int)t64[t * BATCH + b];
            num += trans[pt * NT + ct] + em[(t * BATCH + b) * NT + ct];
        }
    } else {
        for (int t = 1 + j; t < length; t += NT) {
            const int pt = t32[(t - 1) * BATCH + b];
            const int ct = t32[t * BATCH + b];
            num += trans[pt * NT + ct] + em[(t * BATCH + b) * NT + ct];
        }
    }
#pragma unroll
    for (int o = 16; o > 0; o >>= 1)
        num += __shfl_xor_sync(0xffffffffu, num, o);
    if (lane == 0) sh_num[w] = num;

    // ---- init: beta_0 = exp(start + em_0), linear domain ----
    sh_e[0][j] = __expf(startT[j] + em[b * NT + j]);

    // emission prefetch ring: emr[(s-1)&3] holds raw em for step s
    float emr[4];
#pragma unroll
    for (int d = 0; d < 4; ++d)
        emr[d] = (1 + d < length) ? em[((1 + d) * BATCH + b) * NT + j] : 0.f;
    float expCur = __expf(emr[0]);   // exp(em) for step t=1

    int ktot = 0;                    // accumulated power-of-2 renorm exponent
    __syncthreads();

    for (int t = 1; t < length; ++t) {
        // prefetch raw em for step t+4 into slot (t+3)&3 (== (t-1)&3, consumed)
        if (t + 4 < length)
            emr[(t + 3) & 3] = em[((t + 4) * BATCH + b) * NT + j];

        const int prev = (t - 1) & 1;
        const float4* __restrict__ e4 = (const float4*)sh_e[prev];

        // renorm every 4 steps: exact power-of-2 scale from shared beta[0]
        float scale = 1.0f;
        if ((t & 3) == 0) {
            const float v = sh_e[prev][0];
            const int k = ((__float_as_int(v) >> 23) & 0xFF) - 127;
            scale = __int_as_float((127 - k) << 23);   // 2^-k, exact
            ktot += k;
        }

        // dot(beta_prev, exp(T)[:,j]) as 32 packed FFMA2 + ADD2 tree
        unsigned long long s0 = 0ull, s1 = 0ull, s2 = 0ull, s3 = 0ull;
#pragma unroll
        for (int k = 0; k < NT / 4; ++k) {            // 16 float4 loads
            const float4 a = e4[k];
            const unsigned long long p0 = pack2(a.x, a.y);
            const unsigned long long p1 = pack2(a.z, a.w);
            if ((k & 1) == 0) {
                s0 = fma2(p0, eT2[2 * k + 0], s0);
                s1 = fma2(p1, eT2[2 * k + 1], s1);
            } else {
                s2 = fma2(p0, eT2[2 * k + 0], s2);
                s3 = fma2(p1, eT2[2 * k + 1], s3);
            }
        }
        const unsigned long long sp = add2(add2(s0, s1), add2(s2, s3));
        float slo, shi;
        unpack2(sp, slo, shi);
        const float dot = slo + shi;

        const float beta = dot * (expCur * scale);

        // exp(em) for step t+1 (slot t&3 holds em for step t+1)
        expCur = __expf(emr[t & 3]);

        sh_e[t & 1][j] = beta;
        __syncthreads();
    }

    // ---- denominator: ktot*ln2 + log(sum_j beta_j * exp(end_j)) ----
    const float v = sh_e[(length - 1) & 1][j] * __expf(endT[j]);
    float e = v;
#pragma unroll
    for (int o = 16; o > 0; o >>= 1)
        e += __shfl_xor_sync(0xffffffffu, e, o);
    if (lane == 0) sh_sum[w] = e;
    __syncthreads();

    if (j == 0) {
        const double denom = (double)ktot * 0.6931471805599453
                           + (double)logf(sh_sum[0] + sh_sum[1]);
        const int t0 = is64 ? (int)t64[b] : t32[b];
        const int tl = is64 ? (int)t64[(length - 1) * BATCH + b]
                            : t32[(length - 1) * BATCH + b];
        const double numer = (double)(sh_num[0] + sh_num[1])
                           + (double)(startT[t0] + em[b * NT + t0] + endT[tl]);
        g_llh[b] = (float)(numer - denom);
    }
}

// Deterministic fixed-order tree reduction (double accumulation).
__global__ void __launch_bounds__(BATCH)
crf_reduce_kernel(float* __restrict__ out)
{
    __shared__ double sh[BATCH];
    const int i = threadIdx.x;
    sh[i] = (double)g_llh[i];
    __syncthreads();
#pragma unroll
    for (int o = BATCH / 2; o > 0; o >>= 1) {
        if (i < o) sh[i] += sh[i + o];
        __syncthreads();
    }
    if (i == 0) out[0] = (float)sh[0];
}

extern "C" void kernel_launch(void* const* d_in, const int* in_sizes, int n_in,
                              void* d_out, int out_size)
{
    const float* em     = (const float*)d_in[0];
    const void*  tags   = (const void*)d_in[1];
    const int*   mask   = (const int*)d_in[2];
    const float* startT = (const float*)d_in[3];
    const float* endT   = (const float*)d_in[4];
    const float* trans  = (const float*)d_in[5];
    float* out = (float*)d_out;

    crf_forward_kernel<<<BATCH, NT>>>(em, tags, mask, startT, endT, trans);
    crf_reduce_kernel<<<1, BATCH>>>(out);
}